// round 9
// baseline (speedup 1.0000x reference)
#include <cuda_runtime.h>
#include <cuda_bf16.h>
#include <cuda_fp16.h>

// Problem dims (fixed by setup_inputs)
#define Nn 16
#define Cc 4
#define Hh 256
#define Ww 256
#define HW  (Hh * Ww)       // 65536
#define CHW (Cc * HW)       // 262144
#define TOT (Nn * CHW)      // 4194304
#define INFV 1.0e10f
#define NBLK 512            // main-pass blocks (8 rows each, 1 row per warp)

// Scratch (device globals: no allocation allowed)
__device__ __half g_f1h[TOT];           // after C pass: {0,1,4,9, 255=INF} as half
__device__ float2 g_part[NBLK];         // per-block (num, den) partials
__device__ unsigned int g_ctr;          // last-block counter (reset by k_cpass)

__device__ __forceinline__ __half2 U2H(unsigned int u) { return *reinterpret_cast<__half2*>(&u); }
__device__ __forceinline__ unsigned int H2U(__half2 h)  { return *reinterpret_cast<unsigned int*>(&h); }

// ---------------------------------------------------------------------------
// C pass: f1[c] = min_{c'} (c-c')^2 + (t[c']!=0 ? 0 : INF), written as half.
__global__ void k_cpass(const int* __restrict__ tgt) {
    int idx = blockIdx.x * blockDim.x + threadIdx.x;   // over N*H*W/8 = 131072
    if (idx == 0) g_ctr = 0u;
    int n   = idx >> 13;
    int rem = idx & 8191;
    int base = n * CHW + (rem << 3);

    int4 a0a = *(const int4*)(tgt + base          ), a0b = *(const int4*)(tgt + base           + 4);
    int4 a1a = *(const int4*)(tgt + base +     HW ), a1b = *(const int4*)(tgt + base +     HW  + 4);
    int4 a2a = *(const int4*)(tgt + base + 2 * HW ), a2b = *(const int4*)(tgt + base + 2 * HW  + 4);
    int4 a3a = *(const int4*)(tgt + base + 3 * HW ), a3b = *(const int4*)(tgt + base + 3 * HW  + 4);

    float f0[8], f1[8], f2[8], f3[8];
#pragma unroll
    for (int k = 0; k < 8; k++) {
        bool t0 = ((k < 4) ? (&a0a.x)[k] : (&a0b.x)[k - 4]) != 0;
        bool t1 = ((k < 4) ? (&a1a.x)[k] : (&a1b.x)[k - 4]) != 0;
        bool t2 = ((k < 4) ? (&a2a.x)[k] : (&a2b.x)[k - 4]) != 0;
        bool t3 = ((k < 4) ? (&a3a.x)[k] : (&a3b.x)[k - 4]) != 0;
        f0[k] = t0 ? 0.f : (t1 ? 1.f : (t2 ? 4.f : (t3 ? 9.f : 255.f)));
        f1[k] = t1 ? 0.f : ((t0 || t2) ? 1.f : (t3 ? 4.f : 255.f));
        f2[k] = t2 ? 0.f : ((t1 || t3) ? 1.f : (t0 ? 4.f : 255.f));
        f3[k] = t3 ? 0.f : (t2 ? 1.f : (t1 ? 4.f : (t0 ? 9.f : 255.f)));
    }
    uint4 o;
    o = make_uint4(H2U(__floats2half2_rn(f0[0], f0[1])), H2U(__floats2half2_rn(f0[2], f0[3])),
                   H2U(__floats2half2_rn(f0[4], f0[5])), H2U(__floats2half2_rn(f0[6], f0[7])));
    *(uint4*)(g_f1h + base         ) = o;
    o = make_uint4(H2U(__floats2half2_rn(f1[0], f1[1])), H2U(__floats2half2_rn(f1[2], f1[3])),
                   H2U(__floats2half2_rn(f1[4], f1[5])), H2U(__floats2half2_rn(f1[6], f1[7])));
    *(uint4*)(g_f1h + base +     HW) = o;
    o = make_uint4(H2U(__floats2half2_rn(f2[0], f2[1])), H2U(__floats2half2_rn(f2[2], f2[3])),
                   H2U(__floats2half2_rn(f2[4], f2[5])), H2U(__floats2half2_rn(f2[6], f2[7])));
    *(uint4*)(g_f1h + base + 2 * HW) = o;
    o = make_uint4(H2U(__floats2half2_rn(f3[0], f3[1])), H2U(__floats2half2_rn(f3[2], f3[3])),
                   H2U(__floats2half2_rn(f3[4], f3[5])), H2U(__floats2half2_rn(f3[6], f3[7])));
    *(uint4*)(g_f1h + base + 3 * HW) = o;
}

// ---------------------------------------------------------------------------
__device__ __forceinline__ float f1_at(int n, int c, int h, int w) {
    float v = __half2float(g_f1h[((n * Cc + c) << 16) + (h << 8) + w]);
    return (v >= 255.f) ? INFV : v;
}

// Exact H-direction transform at one (n,c,h,w): window + rare full column scan.
__device__ float exact_f2(int n, int c, int h, int w) {
    float m = INFV;
    int j0 = h - 3 < 0 ? 0 : h - 3;
    int j1 = h + 3 > 255 ? 255 : h + 3;
    for (int j = j0; j <= j1; j++) {
        float dj = (float)(j - h);
        m = fminf(m, fmaf(dj, dj, f1_at(n, c, j, w)));
    }
    if (m > 16.0f) {
        m = INFV;
        for (int j = 0; j < Hh; j++) {
            float dj = (float)(j - h);
            m = fminf(m, fmaf(dj, dj, f1_at(n, c, j, w)));
        }
    }
    return m;
}

// Cold: recompute one thread's whole (8-pixel x 4-class) contribution exactly.
__device__ __noinline__ void recompute_unit(int n, int h, int w0,
                                            const float* __restrict__ pred,
                                            float& num, float& den) {
    num = 0.f; den = 0.f;
    for (int k = 0; k < 8; k++) {
        int w = w0 + k;
        float d[4], e[4];
        for (int c = 0; c < 4; c++) {
            float m = INFV;
            int j0 = w - 3 < 0 ? 0 : w - 3;
            int j1 = w + 3 > 255 ? 255 : w + 3;
            for (int j = j0; j <= j1; j++) {
                float dj = (float)(j - w);
                m = fminf(m, fmaf(dj, dj, exact_f2(n, c, h, j)));
            }
            if (m > 16.0f) {
                m = INFV;
                for (int j = 0; j < Ww; j++) {
                    float dj = (float)(j - w);
                    m = fminf(m, fmaf(dj, dj, exact_f2(n, c, h, j)));
                }
            }
            d[c] = sqrtf(m);
            e[c] = __expf(pred[n * CHW + c * HW + (h << 8) + w]);
        }
        float es = e[0] + e[1] + e[2] + e[3];
        num += (e[0] * d[0] + e[1] * d[1] + e[2] * d[2] + e[3] * d[3]) / es;
        den += d[0] + d[1] + d[2] + d[3];
    }
}

__device__ __forceinline__ float fsqrt_approx(float x) {
    float r;
    asm("sqrt.approx.f32 %0, %1;" : "=f"(r) : "f"(x));
    return r;
}

// ---------------------------------------------------------------------------
// Main pass. ONE WARP = ONE (n,h) ROW. Lane owns 8 px (4 half2 columns).
// H-pass: 7 f1h rows per class loaded straight to registers (LDG.128,
// coalesced). W-pass: +-3 halo fetched from neighbor lanes via shfl; shifted
// windows built with PRMT. No __syncthreads in the hot path, no smem tiles.
// Exactness: outside-window cost >= 16 => any result <= 16 is exact; any
// pixel whose true value > 16 gives acc > 16 and trips the one cold check.
__global__ void __launch_bounds__(256, 4) k_main(const float* __restrict__ pred,
                                                 float* __restrict__ out) {
    __shared__ float rnum[8], rden[8];
    __shared__ bool  s_last;

    const __half2 C1 = __float2half2_rn(1.0f);
    const __half2 C4 = __float2half2_rn(4.0f);
    const __half2 C9 = __float2half2_rn(9.0f);
    const unsigned int INFW = 0x5BF85BF8u;    // half2(255, 255)

    int tid  = threadIdx.x;
    int lane = tid & 31, wrp = tid >> 5;
    int gw = (blockIdx.x << 3) + wrp;         // global row id
    int n = gw >> 8, h = gw & 255;
    int w0 = lane << 3;
    int pbase = n * CHW + (h << 8) + w0;

    float se[8]  = {0.f,0.f,0.f,0.f,0.f,0.f,0.f,0.f};
    float sed[8] = {0.f,0.f,0.f,0.f,0.f,0.f,0.f,0.f};
    float den = 0.f;
    __half2 hmx = __float2half2_rn(0.0f);

#pragma unroll
    for (int c = 0; c < 4; c++) {
        // ---- H-direction: 7 rows -> 4 half2 columns ----
        const __half* __restrict__ pc = g_f1h + ((n * Cc + c) << 16) + w0;
        uint4 v[7];
#pragma unroll
        for (int s = 0; s < 7; s++) {
            int j = h - 3 + s;
            v[s] = ((unsigned)j < 256u) ? *(const uint4*)(pc + (j << 8))
                                        : make_uint4(INFW, INFW, INFW, INFW);
        }
        __half2 F0, F1, F2, F3;
        {
            __half2 a;
            a = U2H(v[3].x);
            a = __hmin2(a, __hadd2(__hmin2(U2H(v[2].x), U2H(v[4].x)), C1));
            a = __hmin2(a, __hadd2(__hmin2(U2H(v[1].x), U2H(v[5].x)), C4));
            a = __hmin2(a, __hadd2(__hmin2(U2H(v[0].x), U2H(v[6].x)), C9));
            F0 = a;
            a = U2H(v[3].y);
            a = __hmin2(a, __hadd2(__hmin2(U2H(v[2].y), U2H(v[4].y)), C1));
            a = __hmin2(a, __hadd2(__hmin2(U2H(v[1].y), U2H(v[5].y)), C4));
            a = __hmin2(a, __hadd2(__hmin2(U2H(v[0].y), U2H(v[6].y)), C9));
            F1 = a;
            a = U2H(v[3].z);
            a = __hmin2(a, __hadd2(__hmin2(U2H(v[2].z), U2H(v[4].z)), C1));
            a = __hmin2(a, __hadd2(__hmin2(U2H(v[1].z), U2H(v[5].z)), C4));
            a = __hmin2(a, __hadd2(__hmin2(U2H(v[0].z), U2H(v[6].z)), C9));
            F2 = a;
            a = U2H(v[3].w);
            a = __hmin2(a, __hadd2(__hmin2(U2H(v[2].w), U2H(v[4].w)), C1));
            a = __hmin2(a, __hadd2(__hmin2(U2H(v[1].w), U2H(v[5].w)), C4));
            a = __hmin2(a, __hadd2(__hmin2(U2H(v[0].w), U2H(v[6].w)), C9));
            F3 = a;
        }

        // ---- W-direction: halo via shfl, shifts via PRMT ----
        unsigned int uF0 = H2U(F0), uF1 = H2U(F1), uF2 = H2U(F2), uF3 = H2U(F3);
        unsigned int uL2 = __shfl_up_sync(0xFFFFFFFFu, uF2, 1);
        unsigned int uL3 = __shfl_up_sync(0xFFFFFFFFu, uF3, 1);
        unsigned int uR0 = __shfl_down_sync(0xFFFFFFFFu, uF0, 1);
        unsigned int uR1 = __shfl_down_sync(0xFFFFFFFFu, uF1, 1);
        if (lane == 0)  { uL2 = INFW; uL3 = INFW; }
        if (lane == 31) { uR0 = INFW; uR1 = INFW; }

        unsigned int O0 = __byte_perm(uL3, uF0, 0x5432);   // (y-1, y0)
        unsigned int O1 = __byte_perm(uF0, uF1, 0x5432);   // (y1, y2)
        unsigned int O2 = __byte_perm(uF1, uF2, 0x5432);   // (y3, y4)
        unsigned int O3 = __byte_perm(uF2, uF3, 0x5432);   // (y5, y6)
        unsigned int O4 = __byte_perm(uF3, uR0, 0x5432);   // (y7, y8)
        unsigned int M3 = __byte_perm(uL2, uL3, 0x5432);   // (y-3, y-2)
        unsigned int P3 = __byte_perm(uR0, uR1, 0x5432);   // (y9, y10)

        __half2 a0 = F0, a1 = F1, a2 = F2, a3 = F3;
        a0 = __hmin2(a0, __hadd2(__hmin2(U2H(O0), U2H(O1)), C1));
        a1 = __hmin2(a1, __hadd2(__hmin2(U2H(O1), U2H(O2)), C1));
        a2 = __hmin2(a2, __hadd2(__hmin2(U2H(O2), U2H(O3)), C1));
        a3 = __hmin2(a3, __hadd2(__hmin2(U2H(O3), U2H(O4)), C1));
        a0 = __hmin2(a0, __hadd2(__hmin2(U2H(uL3), F1), C4));
        a1 = __hmin2(a1, __hadd2(__hmin2(F0, F2), C4));
        a2 = __hmin2(a2, __hadd2(__hmin2(F1, F3), C4));
        a3 = __hmin2(a3, __hadd2(__hmin2(F2, U2H(uR0)), C4));
        a0 = __hmin2(a0, __hadd2(__hmin2(U2H(M3), U2H(O2)), C9));
        a1 = __hmin2(a1, __hadd2(__hmin2(U2H(O0), U2H(O3)), C9));
        a2 = __hmin2(a2, __hadd2(__hmin2(U2H(O1), U2H(O4)), C9));
        a3 = __hmin2(a3, __hadd2(__hmin2(U2H(O2), U2H(P3)), C9));

        hmx = __hmax2(hmx, __hmax2(__hmax2(a0, a1), __hmax2(a2, a3)));

        float2 fA = __half22float2(a0), fB = __half22float2(a1);
        float2 fC = __half22float2(a2), fD = __half22float2(a3);
        float d0 = fsqrt_approx(fA.x), d1 = fsqrt_approx(fA.y);
        float d2 = fsqrt_approx(fB.x), d3 = fsqrt_approx(fB.y);
        float d4 = fsqrt_approx(fC.x), d5 = fsqrt_approx(fC.y);
        float d6 = fsqrt_approx(fD.x), d7 = fsqrt_approx(fD.y);

        float4 xa = *(const float4*)(pred + pbase + c * HW);
        float4 xb = *(const float4*)(pred + pbase + c * HW + 4);
        float e0 = __expf(xa.x), e1 = __expf(xa.y), e2 = __expf(xa.z), e3 = __expf(xa.w);
        float e4 = __expf(xb.x), e5 = __expf(xb.y), e6 = __expf(xb.z), e7 = __expf(xb.w);
        se[0] += e0; se[1] += e1; se[2] += e2; se[3] += e3;
        se[4] += e4; se[5] += e5; se[6] += e6; se[7] += e7;
        sed[0] += e0 * d0; sed[1] += e1 * d1; sed[2] += e2 * d2; sed[3] += e3 * d3;
        sed[4] += e4 * d4; sed[5] += e5 * d5; sed[6] += e6 * d6; sed[7] += e7 * d7;
        den += (d0 + d1) + (d2 + d3) + (d4 + d5) + (d6 + d7);
    }

    float num = __fdividef(sed[0], se[0]) + __fdividef(sed[1], se[1]) +
                __fdividef(sed[2], se[2]) + __fdividef(sed[3], se[3]) +
                __fdividef(sed[4], se[4]) + __fdividef(sed[5], se[5]) +
                __fdividef(sed[6], se[6]) + __fdividef(sed[7], se[7]);

    float chk = fmaxf(__half2float(__low2half(hmx)), __half2float(__high2half(hmx)));
    if (chk > 16.0f)     // astronomically cold: redo this unit exactly
        recompute_unit(n, h, w0, pred, num, den);

    // ---- block reduce (one barrier per block) ----
#pragma unroll
    for (int o = 16; o; o >>= 1) {
        num += __shfl_xor_sync(0xFFFFFFFFu, num, o);
        den += __shfl_xor_sync(0xFFFFFFFFu, den, o);
    }
    if (lane == 0) { rnum[wrp] = num; rden[wrp] = den; }
    __syncthreads();
    if (wrp == 0) {
        num = (lane < 8) ? rnum[lane] : 0.f;
        den = (lane < 8) ? rden[lane] : 0.f;
#pragma unroll
        for (int o = 4; o; o >>= 1) {
            num += __shfl_xor_sync(0xFFFFFFFFu, num, o);
            den += __shfl_xor_sync(0xFFFFFFFFu, den, o);
        }
        if (lane == 0) g_part[blockIdx.x] = make_float2(num, den);
    }

    // ---- last-block final reduction ----
    __threadfence();
    if (threadIdx.x == 0) {
        unsigned int prevc = atomicAdd(&g_ctr, 1u);
        s_last = (prevc == (unsigned int)(NBLK - 1));
    }
    __syncthreads();
    if (!s_last) return;

    __shared__ double snum[8], sden[8];
    double dn = 0.0, dd = 0.0;
#pragma unroll
    for (int q = 0; q < NBLK / 256; q++) {
        float2 p = g_part[q * 256 + tid];
        dn += (double)p.x;
        dd += (double)p.y;
    }
#pragma unroll
    for (int o = 16; o; o >>= 1) {
        dn += __shfl_xor_sync(0xFFFFFFFFu, dn, o);
        dd += __shfl_xor_sync(0xFFFFFFFFu, dd, o);
    }
    if (lane == 0) { snum[wrp] = dn; sden[wrp] = dd; }
    __syncthreads();
    if (wrp == 0) {
        dn = (lane < 8) ? snum[lane] : 0.0;
        dd = (lane < 8) ? sden[lane] : 0.0;
#pragma unroll
        for (int o = 4; o; o >>= 1) {
            dn += __shfl_xor_sync(0xFFFFFFFFu, dn, o);
            dd += __shfl_xor_sync(0xFFFFFFFFu, dd, o);
        }
        if (lane == 0) out[0] = (float)(dn / (dd + 1e-10));
    }
}

// ---------------------------------------------------------------------------
extern "C" void kernel_launch(void* const* d_in, const int* in_sizes, int n_in,
                              void* d_out, int out_size) {
    const float* pred = (const float*)d_in[0];
    const int*   tgt  = (const int*)d_in[1];
    float*       out  = (float*)d_out;

    k_cpass<<<(Nn * HW / 8) / 256, 256>>>(tgt);
    k_main<<<NBLK, 256>>>(pred, out);
}